// round 16
// baseline (speedup 1.0000x reference)
#include <cuda_runtime.h>
#include <cuda_fp16.h>
#include <math.h>

// Fixed shapes: B x 3 x 512 x 960
#define IMG_H 512
#define IMG_W 960
#define NCH 3

#define TW 32
#define TH 32          // warp owns a 4-row strip (8 warps x 4 rows)

#define ALPHA 0.85f
#define C1 (0.01f * 0.01f)
#define C2 (0.03f * 0.03f)
#define EPS2 (0.001f * 0.001f)

__device__ double g_accP = 0.0, g_accL = 0.0, g_accD = 0.0;
__device__ unsigned int g_ticket = 0;

__device__ __forceinline__ float fast_sqrt_pos(float x) {
    return x * rsqrtf(x);   // x >= EPS2 > 0
}

typedef unsigned long long ull;
__device__ __forceinline__ ull f2u(float2 v) {
    ull u; asm("mov.b64 %0, {%1, %2};" : "=l"(u) : "f"(v.x), "f"(v.y)); return u;
}
__device__ __forceinline__ float2 u2f(ull u) {
    float2 v; asm("mov.b64 {%0, %1}, %2;" : "=f"(v.x), "=f"(v.y) : "l"(u)); return v;
}
__device__ __forceinline__ ull x2add(ull a, ull b) {
    ull r; asm("add.rn.f32x2 %0, %1, %2;" : "=l"(r) : "l"(a), "l"(b)); return r;
}
__device__ __forceinline__ ull x2mul(ull a, ull b) {
    ull r; asm("mul.rn.f32x2 %0, %1, %2;" : "=l"(r) : "l"(a), "l"(b)); return r;
}
__device__ __forceinline__ ull x2fma(ull a, ull b, ull c) {
    ull r; asm("fma.rn.f32x2 %0, %1, %2, %3;" : "=l"(r) : "l"(a), "l"(b), "l"(c)); return r;
}

// packed SSIM consume for a pair of outputs; adds clipped (1-ssim)/2 into ss[2], charb into l1[2]
__device__ __forceinline__ void ssim_consume(
    __half2 vA01, __half2 vA23, __half2 vA4,
    __half2 vB01, __half2 vB23, __half2 vB4,
    __half2 cabA, __half2 cabB, ull uinv,
    float* ss, float* l1)
{
    const ull UNEG1 = f2u(make_float2(-1.0f, -1.0f));
    const ull UTWO  = f2u(make_float2(2.0f, 2.0f));
    const ull UC1   = f2u(make_float2(C1, C1));
    const ull UC2   = f2u(make_float2(C2, C2));
    const ull UEPSD = f2u(make_float2(1e-12f, 1e-12f));
    const ull UEPS2 = f2u(make_float2(EPS2, EPS2));

    float2 sA01 = __half22float2(vA01), sB01 = __half22float2(vB01);
    float2 sA23 = __half22float2(vA23), sB23 = __half22float2(vB23);
    float2 sA4  = __half22float2(vA4),  sB4  = __half22float2(vB4);

    ull sx  = f2u(make_float2(sA01.x, sB01.x));
    ull sy  = f2u(make_float2(sA01.y, sB01.y));
    ull sxx = f2u(make_float2(sA23.x, sB23.x));
    ull syy = f2u(make_float2(sA23.y, sB23.y));
    ull sxy = f2u(make_float2(sA4.x,  sB4.x));

    ull mux  = x2mul(sx, uinv);
    ull muy  = x2mul(sy, uinv);
    ull nmux = x2mul(mux, UNEG1);
    ull nmuy = x2mul(muy, UNEG1);
    ull sigx  = x2fma(nmux, mux, x2mul(sxx, uinv));
    ull sigy  = x2fma(nmuy, muy, x2mul(syy, uinv));
    ull sigxy = x2fma(nmux, muy, x2mul(sxy, uinv));
    ull mm   = x2mul(mux, muy);
    ull num  = x2mul(x2fma(mm, UTWO, UC1), x2fma(sigxy, UTWO, UC2));
    ull den1 = x2fma(mux, mux, x2fma(muy, muy, UC1));
    ull den2 = x2add(x2add(sigx, sigy), UC2);
    ull den  = x2fma(den1, den2, UEPSD);
    float2 fn = u2f(num), fd = u2f(den);
    float ssim0 = __fdividef(fn.x, fd.x);
    float ssim1 = __fdividef(fn.y, fd.y);
    ss[0] += fminf(fmaxf((1.0f - ssim0) * 0.5f, 0.0f), 1.0f);
    ss[1] += fminf(fmaxf((1.0f - ssim1) * 0.5f, 0.0f), 1.0f);

    float2 ccA = __half22float2(cabA);
    float2 ccB = __half22float2(cabB);
    ull dpair = f2u(make_float2(ccA.x - ccA.y, ccB.x - ccB.y));
    float2 dc = u2f(x2fma(dpair, dpair, UEPS2));
    l1[0] += fast_sqrt_pos(dc.x);
    l1[1] += fast_sqrt_pos(dc.y);
}

__global__ __launch_bounds__(256, 6) void stereo_loss_kernel(
    const float* __restrict__ left,
    const float* __restrict__ right,
    const float* __restrict__ d_left,
    const float* __restrict__ d_right,
    const float* __restrict__ nonocc,
    float* __restrict__ out,
    int nblocks, int total_px)
{
    const int W = IMG_W, H = IMG_H;
    __shared__ __half2 sAB[NCH][TH + 2][TW + 2];   // (left, warped right) fp16
    __shared__ float   sD[TH + 2][TW + 2];          // d_left fp32

    const int w0 = blockIdx.x * TW;
    const int h0 = blockIdx.y * TH;
    const int b  = blockIdx.z;

    const size_t planeHW = (size_t)H * W;
    const float* Lb  = left    + (size_t)b * NCH * planeHW;
    const float* Rb  = right   + (size_t)b * NCH * planeHW;
    const float* Db  = d_left  + (size_t)b * planeHW;
    const float* DRb = d_right + (size_t)b * planeHW;
    const float* Nb  = nonocc  + (size_t)b * planeHW;

    // ---- halo fill ----
    for (int idx = threadIdx.x; idx < (TH + 2) * (TW + 2); idx += 256) {
        int i = idx / (TW + 2);
        int j = idx - i * (TW + 2);
        int gh = h0 - 1 + i;
        int gw = w0 - 1 + j;
        if (gh >= 0 && gh < H && gw >= 0 && gw < W) {
            float d = Db[(size_t)gh * W + gw];
            sD[i][j] = d;
            float x  = (float)gw - d;
            float x0 = floorf(x);
            float wx = x - x0;
            int   xi = (int)x0;
            int x0i = min(max(xi, 0), W - 1);
            int x1i = min(max(xi + 1, 0), W - 1);
            const float* rrow = Rb + (size_t)gh * W;
            const float* lrow = Lb + (size_t)gh * W;
            #pragma unroll
            for (int c = 0; c < NCH; c++) {
                float v0 = rrow[(size_t)c * planeHW + x0i];
                float v1 = rrow[(size_t)c * planeHW + x1i];
                float bb = (1.0f - wx) * v0 + wx * v1;
                float aa = lrow[(size_t)c * planeHW + gw];
                sAB[c][i][j] = __floats2half2_rn(aa, bb);
            }
        } else {
            sD[i][j] = 0.0f;
            #pragma unroll
            for (int c = 0; c < NCH; c++) sAB[c][i][j] = __floats2half2_rn(0.0f, 0.0f);
        }
    }
    __syncthreads();

    const int tx  = threadIdx.x & 31;
    const int wid = threadIdx.x >> 5;
    const int r0  = wid * 4;                // first output row of this warp (0..28)
    const int gw  = w0 + tx;

    // ---- per-row validity / weight ----
    float wv[4];
    float accD = 0.0f;
    const bool colsIn = (gw > 0) & (gw < W - 1);
    float invk[4];
    #pragma unroll
    for (int k = 0; k < 4; k++) {
        const int gh = h0 + r0 + k;
        float dl = sD[r0 + k + 1][tx + 1];
        float x  = (float)gw - dl;
        float gx = 2.0f * x / (float)(W - 1) - 1.0f;
        float vb = (gx >= -1.0f && gx <= 1.0f) ? 1.0f : 0.0f;
        wv[k] = vb * Nb[(size_t)gh * W + gw];
        accD += wv[k];
        const bool rowsIn = (gh > 0) & (gh < H - 1);
        invk[k] = rowsIn ? (colsIn ? (1.0f / 9.0f) : (1.0f / 6.0f))
                         : (colsIn ? (1.0f / 6.0f) : (1.0f / 4.0f));
    }
    const ull uinv01 = f2u(make_float2(invk[0], invk[1]));
    const ull uinv23 = f2u(make_float2(invk[2], invk[3]));

    float ssum[4]  = {0.f, 0.f, 0.f, 0.f};
    float l1sum[4] = {0.f, 0.f, 0.f, 0.f};

    const __half2 HZERO = __floats2half2_rn(0.0f, 0.0f);

    #pragma unroll
    for (int c = 0; c < NCH; c++) {
        // ---- block A: staging rows q=0..3 -> outputs k=0,1 ----
        __half2 v01_0 = HZERO, v23_0 = HZERO, v4_0 = HZERO;
        __half2 v01_1 = HZERO, v23_1 = HZERO, v4_1 = HZERO;
        __half2 h01_2, h23_2, h4_2, h01_3, h23_3, h4_3;   // saved rows q=2,3
        __half2 cab0 = HZERO, cab1 = HZERO, cab2 = HZERO;
        #pragma unroll
        for (int q = 0; q < 4; q++) {
            const int sr = r0 + q;
            __half2 p0 = sAB[c][sr][tx];
            __half2 p1 = sAB[c][sr][tx + 1];
            __half2 p2 = sAB[c][sr][tx + 2];
            __half2 h01 = __hadd2(__hadd2(p0, p1), p2);
            __half2 h23 = __hfma2(p0, p0, __hfma2(p1, p1, __hmul2(p2, p2)));
            __half2 hx  = __hfma2(p0, __lowhigh2highlow(p0),
                          __hfma2(p1, __lowhigh2highlow(p1),
                          __hmul2(p2, __lowhigh2highlow(p2))));
            if (q < 3) { v01_0 = __hadd2(v01_0, h01); v23_0 = __hadd2(v23_0, h23); v4_0 = __hadd2(v4_0, hx); }
            if (q >= 1) { v01_1 = __hadd2(v01_1, h01); v23_1 = __hadd2(v23_1, h23); v4_1 = __hadd2(v4_1, hx); }
            if (q == 1) cab0 = p1;
            if (q == 2) { cab1 = p1; h01_2 = h01; h23_2 = h23; h4_2 = hx; }
            if (q == 3) { cab2 = p1; h01_3 = h01; h23_3 = h23; h4_3 = hx; }
        }
        ssim_consume(v01_0, v23_0, v4_0, v01_1, v23_1, v4_1, cab0, cab1, uinv01, ssum, l1sum);

        // ---- block B: staging rows q=2..5 -> outputs k=2,3 (reuse h rows 2,3) ----
        __half2 cab3;
        {
            // q=4
            const int sr4 = r0 + 4;
            __half2 p0 = sAB[c][sr4][tx];
            __half2 p1 = sAB[c][sr4][tx + 1];
            __half2 p2 = sAB[c][sr4][tx + 2];
            __half2 h01_4 = __hadd2(__hadd2(p0, p1), p2);
            __half2 h23_4 = __hfma2(p0, p0, __hfma2(p1, p1, __hmul2(p2, p2)));
            __half2 h4_4  = __hfma2(p0, __lowhigh2highlow(p0),
                            __hfma2(p1, __lowhigh2highlow(p1),
                            __hmul2(p2, __lowhigh2highlow(p2))));
            cab3 = p1;
            // q=5
            const int sr5 = r0 + 5;
            __half2 q0 = sAB[c][sr5][tx];
            __half2 q1 = sAB[c][sr5][tx + 1];
            __half2 q2 = sAB[c][sr5][tx + 2];
            __half2 h01_5 = __hadd2(__hadd2(q0, q1), q2);
            __half2 h23_5 = __hfma2(q0, q0, __hfma2(q1, q1, __hmul2(q2, q2)));
            __half2 h4_5  = __hfma2(q0, __lowhigh2highlow(q0),
                            __hfma2(q1, __lowhigh2highlow(q1),
                            __hmul2(q2, __lowhigh2highlow(q2))));
            __half2 w01_2 = __hadd2(__hadd2(h01_2, h01_3), h01_4);
            __half2 w23_2 = __hadd2(__hadd2(h23_2, h23_3), h23_4);
            __half2 w4_2  = __hadd2(__hadd2(h4_2,  h4_3),  h4_4);
            __half2 w01_3 = __hadd2(__hadd2(h01_3, h01_4), h01_5);
            __half2 w23_3 = __hadd2(__hadd2(h23_3, h23_4), h23_5);
            __half2 w4_3  = __hadd2(__hadd2(h4_3,  h4_4),  h4_5);
            ssim_consume(w01_2, w23_2, w4_2, w01_3, w23_3, w4_3, cab2, cab3, uinv23, ssum + 2, l1sum + 2);
        }
    }

    // ---- finalize rows: photo + LR consistency ----
    float accP = 0.0f, accL = 0.0f;
    #pragma unroll
    for (int k = 0; k < 4; k++) {
        float photo = (ALPHA * (1.0f / 3.0f)) * ssum[k] +
                      ((1.0f - ALPHA) * (1.0f / 3.0f)) * l1sum[k];
        accP += photo * wv[k];
        if (wv[k] != 0.0f) {
            const int gh = h0 + r0 + k;
            float dl  = sD[r0 + k + 1][tx + 1];
            float x   = (float)gw - dl;
            float x0f = floorf(x);
            float wx  = x - x0f;
            int   xi  = (int)x0f;
            int x0i = min(max(xi, 0), W - 1);
            int x1i = min(max(xi + 1, 0), W - 1);
            const float* drow = DRb + (size_t)gh * W;
            float drw = (1.0f - wx) * drow[x0i] + wx * drow[x1i];
            float dd = dl - drw;
            accL += fast_sqrt_pos(fmaf(dd, dd, EPS2)) * wv[k];
        }
    }

    // ---- block reduction ----
    #pragma unroll
    for (int o = 16; o > 0; o >>= 1) {
        accP += __shfl_down_sync(0xFFFFFFFFu, accP, o);
        accL += __shfl_down_sync(0xFFFFFFFFu, accL, o);
        accD += __shfl_down_sync(0xFFFFFFFFu, accD, o);
    }
    __shared__ float red[3][8];
    const int lane = threadIdx.x & 31;
    if (lane == 0) { red[0][wid] = accP; red[1][wid] = accL; red[2][wid] = accD; }
    __syncthreads();

    __shared__ bool is_last;
    if (threadIdx.x == 0) {
        float p = 0.f, l = 0.f, d = 0.f;
        #pragma unroll
        for (int i = 0; i < 8; i++) { p += red[0][i]; l += red[1][i]; d += red[2][i]; }
        atomicAdd(&g_accP, (double)p);
        atomicAdd(&g_accL, (double)l);
        atomicAdd(&g_accD, (double)d);
        __threadfence();
        unsigned int t = atomicAdd(&g_ticket, 1u);
        is_last = (t == (unsigned int)(nblocks - 1));
    }
    __syncthreads();

    if (is_last && threadIdx.x == 0) {
        __threadfence();
        double tp = atomicAdd(&g_accP, 0.0);
        double tl = atomicAdd(&g_accL, 0.0);
        double td = atomicAdd(&g_accD, 0.0);
        double photo = tp / (td + 1e-6);
        double lr    = tl / (td + 1e-6);
        out[0] = (float)(photo + 0.2 * lr);
        out[1] = (float)photo;
        out[2] = (float)lr;
        out[3] = (float)(td / (double)total_px);
        g_accP = 0.0; g_accL = 0.0; g_accD = 0.0;
        __threadfence();
        g_ticket = 0;
    }
}

extern "C" void kernel_launch(void* const* d_in, const int* in_sizes, int n_in,
                              void* d_out, int out_size) {
    const float* left    = (const float*)d_in[0];
    const float* right   = (const float*)d_in[1];
    const float* d_left  = (const float*)d_in[2];
    const float* d_right = (const float*)d_in[3];
    const float* nonocc  = (const float*)d_in[4];
    float* out = (float*)d_out;

    int B = in_sizes[2] / (IMG_H * IMG_W);   // d_left is [B,1,H,W]

    dim3 grid(IMG_W / TW, IMG_H / TH, B);    // 30 x 16 x B
    int nblocks = grid.x * grid.y * grid.z;

    stereo_loss_kernel<<<grid, 256>>>(left, right, d_left, d_right, nonocc,
                                      out, nblocks, B * IMG_H * IMG_W);
}

// round 17
// speedup vs baseline: 1.0027x; 1.0027x over previous
#include <cuda_runtime.h>
#include <cuda_fp16.h>
#include <math.h>

// Fixed shapes: B x 3 x 512 x 960
#define IMG_H 512
#define IMG_W 960
#define NCH 3

#define TW 32
#define TH 16

#define ALPHA 0.85f
#define C1 (0.01f * 0.01f)
#define C2 (0.03f * 0.03f)
#define EPS2 (0.001f * 0.001f)

__device__ double g_accP = 0.0, g_accL = 0.0, g_accD = 0.0;
__device__ unsigned int g_ticket = 0;

__device__ __forceinline__ float fast_sqrt_pos(float x) {
    return x * rsqrtf(x);   // x >= EPS2 > 0
}

typedef unsigned long long ull;
__device__ __forceinline__ ull f2u(float2 v) {
    ull u; asm("mov.b64 %0, {%1, %2};" : "=l"(u) : "f"(v.x), "f"(v.y)); return u;
}
__device__ __forceinline__ float2 u2f(ull u) {
    float2 v; asm("mov.b64 {%0, %1}, %2;" : "=f"(v.x), "=f"(v.y) : "l"(u)); return v;
}
__device__ __forceinline__ ull x2add(ull a, ull b) {
    ull r; asm("add.rn.f32x2 %0, %1, %2;" : "=l"(r) : "l"(a), "l"(b)); return r;
}
__device__ __forceinline__ ull x2mul(ull a, ull b) {
    ull r; asm("mul.rn.f32x2 %0, %1, %2;" : "=l"(r) : "l"(a), "l"(b)); return r;
}
__device__ __forceinline__ ull x2fma(ull a, ull b, ull c) {
    ull r; asm("fma.rn.f32x2 %0, %1, %2, %3;" : "=l"(r) : "l"(a), "l"(b), "l"(c)); return r;
}

__global__ __launch_bounds__(256, 7) void stereo_loss_kernel(
    const float* __restrict__ left,
    const float* __restrict__ right,
    const float* __restrict__ d_left,
    const float* __restrict__ d_right,
    const float* __restrict__ nonocc,
    float* __restrict__ out,
    int nblocks, int total_px)
{
    const int W = IMG_W, H = IMG_H;
    // packed fp16 pair: low = left, high = warped right (4 B/pixel)
    __shared__ __half2 sAB[NCH][TH + 2][TW + 2];
    __shared__ float   sD[TH + 2][TW + 2];        // d_left stays fp32

    const int w0 = blockIdx.x * TW;
    const int h0 = blockIdx.y * TH;
    const int b  = blockIdx.z;

    const size_t planeHW = (size_t)H * W;
    const float* Lb  = left    + (size_t)b * NCH * planeHW;
    const float* Rb  = right   + (size_t)b * NCH * planeHW;
    const float* Db  = d_left  + (size_t)b * planeHW;
    const float* DRb = d_right + (size_t)b * planeHW;
    const float* Nb  = nonocc  + (size_t)b * planeHW;

    // ---- halo fill (zero outside image) ----
    for (int idx = threadIdx.x; idx < (TH + 2) * (TW + 2); idx += 256) {
        int i = idx / (TW + 2);
        int j = idx - i * (TW + 2);
        int gh = h0 - 1 + i;
        int gw = w0 - 1 + j;
        if (gh >= 0 && gh < H && gw >= 0 && gw < W) {
            float d = Db[(size_t)gh * W + gw];
            sD[i][j] = d;
            float x  = (float)gw - d;
            float x0 = floorf(x);
            float wx = x - x0;
            int   xi = (int)x0;
            int x0i = min(max(xi, 0), W - 1);
            int x1i = min(max(xi + 1, 0), W - 1);
            const float* rrow = Rb + (size_t)gh * W;
            const float* lrow = Lb + (size_t)gh * W;
            #pragma unroll
            for (int c = 0; c < NCH; c++) {
                float v0 = rrow[(size_t)c * planeHW + x0i];
                float v1 = rrow[(size_t)c * planeHW + x1i];
                float bb = (1.0f - wx) * v0 + wx * v1;
                float aa = lrow[(size_t)c * planeHW + gw];
                sAB[c][i][j] = __floats2half2_rn(aa, bb);
            }
        } else {
            sD[i][j] = 0.0f;
            #pragma unroll
            for (int c = 0; c < NCH; c++) sAB[c][i][j] = __floats2half2_rn(0.0f, 0.0f);
        }
    }
    __syncthreads();

    const int tx  = threadIdx.x & 31;
    const int wid = threadIdx.x >> 5;
    const int r0  = wid * 2;                // first output row (0..14)
    const int gw  = w0 + tx;

    // ---- per-row validity / weight; pool-count reciprocal from constants ----
    float wv[2];
    float accD = 0.0f;
    const bool colsIn = (gw > 0) & (gw < W - 1);
    float invk[2];
    #pragma unroll
    for (int k = 0; k < 2; k++) {
        const int gh = h0 + r0 + k;
        float dl = sD[r0 + k + 1][tx + 1];
        float x  = (float)gw - dl;
        float gx = 2.0f * x / (float)(W - 1) - 1.0f;
        float vb = (gx >= -1.0f && gx <= 1.0f) ? 1.0f : 0.0f;
        wv[k] = vb * Nb[(size_t)gh * W + gw];
        accD += wv[k];
        const bool rowsIn = (gh > 0) & (gh < H - 1);
        invk[k] = rowsIn ? (colsIn ? (1.0f / 9.0f) : (1.0f / 6.0f))
                         : (colsIn ? (1.0f / 6.0f) : (1.0f / 4.0f));
    }

    const ull UNEG1 = f2u(make_float2(-1.0f, -1.0f));
    const ull UTWO  = f2u(make_float2(2.0f, 2.0f));
    const ull UC1   = f2u(make_float2(C1, C1));
    const ull UC2   = f2u(make_float2(C2, C2));
    const ull UEPSD = f2u(make_float2(1e-12f, 1e-12f));
    const ull UEPS2 = f2u(make_float2(EPS2, EPS2));
    const ull uinv  = f2u(make_float2(invk[0], invk[1]));

    float ssum[2]  = {0.f, 0.f};
    float l1sum[2] = {0.f, 0.f};

    #pragma unroll
    for (int c = 0; c < NCH; c++) {
        // shared-middle vertical windowing: v0 = h0+h1+h2, v1 = h1+h2+h3
        // using mid = h1+h2 (3 adds per moment instead of 6)
        __half2 v01_0, v23_0, v4_0;          // holds h0, then final window-0 sums
        __half2 m01, m23, m4;                // mid = h1 + h2
        __half2 v01_1, v23_1, v4_1;          // final window-1 sums
        __half2 cab0, cab1;
        #pragma unroll
        for (int q = 0; q < 4; q++) {
            const int sr = r0 + q;
            __half2 p0 = sAB[c][sr][tx];
            __half2 p1 = sAB[c][sr][tx + 1];
            __half2 p2 = sAB[c][sr][tx + 2];
            __half2 h01 = __hadd2(__hadd2(p0, p1), p2);
            __half2 h23 = __hfma2(p0, p0, __hfma2(p1, p1, __hmul2(p2, p2)));
            __half2 hx  = __hfma2(p0, __lowhigh2highlow(p0),
                          __hfma2(p1, __lowhigh2highlow(p1),
                          __hmul2(p2, __lowhigh2highlow(p2))));
            if (q == 0) { v01_0 = h01; v23_0 = h23; v4_0 = hx; }
            if (q == 1) { m01 = h01; m23 = h23; m4 = hx; cab0 = p1; }
            if (q == 2) {
                m01 = __hadd2(m01, h01); m23 = __hadd2(m23, h23); m4 = __hadd2(m4, hx);
                v01_0 = __hadd2(v01_0, m01); v23_0 = __hadd2(v23_0, m23); v4_0 = __hadd2(v4_0, m4);
                cab1 = p1;
            }
            if (q == 3) {
                v01_1 = __hadd2(m01, h01); v23_1 = __hadd2(m23, h23); v4_1 = __hadd2(m4, hx);
            }
        }

        // ---- convert window sums to fp32; SSIM consume packed across the two rows ----
        float2 s01_0 = __half22float2(v01_0);
        float2 s01_1 = __half22float2(v01_1);
        float2 s23_0 = __half22float2(v23_0);
        float2 s23_1 = __half22float2(v23_1);
        float2 s4_0  = __half22float2(v4_0);
        float2 s4_1  = __half22float2(v4_1);

        ull sx  = f2u(make_float2(s01_0.x, s01_1.x));
        ull sy  = f2u(make_float2(s01_0.y, s01_1.y));
        ull sxx = f2u(make_float2(s23_0.x, s23_1.x));
        ull syy = f2u(make_float2(s23_0.y, s23_1.y));
        ull sxy = f2u(make_float2(s4_0.x, s4_1.x));

        ull mux  = x2mul(sx, uinv);
        ull muy  = x2mul(sy, uinv);
        ull nmux = x2mul(mux, UNEG1);
        ull nmuy = x2mul(muy, UNEG1);
        ull sigx  = x2fma(nmux, mux, x2mul(sxx, uinv));
        ull sigy  = x2fma(nmuy, muy, x2mul(syy, uinv));
        ull sigxy = x2fma(nmux, muy, x2mul(sxy, uinv));
        ull mm   = x2mul(mux, muy);
        ull num  = x2mul(x2fma(mm, UTWO, UC1), x2fma(sigxy, UTWO, UC2));
        ull den1 = x2fma(mux, mux, x2fma(muy, muy, UC1));
        ull den2 = x2add(x2add(sigx, sigy), UC2);
        ull den  = x2fma(den1, den2, UEPSD);
        float2 fn = u2f(num), fd = u2f(den);
        float ssim0 = __fdividef(fn.x, fd.x);
        float ssim1 = __fdividef(fn.y, fd.y);
        ssum[0] += fminf(fmaxf((1.0f - ssim0) * 0.5f, 0.0f), 1.0f);
        ssum[1] += fminf(fmaxf((1.0f - ssim1) * 0.5f, 0.0f), 1.0f);

        // ---- charbonnier L1, packed pair (row0, row1) ----
        float2 cc0 = __half22float2(cab0);
        float2 cc1 = __half22float2(cab1);
        ull dpair = f2u(make_float2(cc0.x - cc0.y, cc1.x - cc1.y));
        float2 dc = u2f(x2fma(dpair, dpair, UEPS2));
        l1sum[0] += fast_sqrt_pos(dc.x);
        l1sum[1] += fast_sqrt_pos(dc.y);
    }

    // ---- finalize rows: photo + LR consistency (fp32 path, from sD) ----
    float accP = 0.0f, accL = 0.0f;
    #pragma unroll
    for (int k = 0; k < 2; k++) {
        float photo = (ALPHA * (1.0f / 3.0f)) * ssum[k] +
                      ((1.0f - ALPHA) * (1.0f / 3.0f)) * l1sum[k];
        accP += photo * wv[k];
        if (wv[k] != 0.0f) {
            const int gh = h0 + r0 + k;
            float dl  = sD[r0 + k + 1][tx + 1];
            float x   = (float)gw - dl;
            float x0f = floorf(x);
            float wx  = x - x0f;
            int   xi  = (int)x0f;
            int x0i = min(max(xi, 0), W - 1);
            int x1i = min(max(xi + 1, 0), W - 1);
            const float* drow = DRb + (size_t)gh * W;
            float drw = (1.0f - wx) * drow[x0i] + wx * drow[x1i];
            float dd = dl - drw;
            accL += fast_sqrt_pos(fmaf(dd, dd, EPS2)) * wv[k];
        }
    }

    // ---- block reduction ----
    #pragma unroll
    for (int o = 16; o > 0; o >>= 1) {
        accP += __shfl_down_sync(0xFFFFFFFFu, accP, o);
        accL += __shfl_down_sync(0xFFFFFFFFu, accL, o);
        accD += __shfl_down_sync(0xFFFFFFFFu, accD, o);
    }
    __shared__ float red[3][8];
    const int lane = threadIdx.x & 31;
    if (lane == 0) { red[0][wid] = accP; red[1][wid] = accL; red[2][wid] = accD; }
    __syncthreads();

    __shared__ bool is_last;
    if (threadIdx.x == 0) {
        float p = 0.f, l = 0.f, d = 0.f;
        #pragma unroll
        for (int i = 0; i < 8; i++) { p += red[0][i]; l += red[1][i]; d += red[2][i]; }
        atomicAdd(&g_accP, (double)p);
        atomicAdd(&g_accL, (double)l);
        atomicAdd(&g_accD, (double)d);
        __threadfence();
        unsigned int t = atomicAdd(&g_ticket, 1u);
        is_last = (t == (unsigned int)(nblocks - 1));
    }
    __syncthreads();

    if (is_last && threadIdx.x == 0) {
        __threadfence();
        double tp = atomicAdd(&g_accP, 0.0);
        double tl = atomicAdd(&g_accL, 0.0);
        double td = atomicAdd(&g_accD, 0.0);
        double photo = tp / (td + 1e-6);
        double lr    = tl / (td + 1e-6);
        out[0] = (float)(photo + 0.2 * lr);
        out[1] = (float)photo;
        out[2] = (float)lr;
        out[3] = (float)(td / (double)total_px);
        g_accP = 0.0; g_accL = 0.0; g_accD = 0.0;
        __threadfence();
        g_ticket = 0;
    }
}

extern "C" void kernel_launch(void* const* d_in, const int* in_sizes, int n_in,
                              void* d_out, int out_size) {
    const float* left    = (const float*)d_in[0];
    const float* right   = (const float*)d_in[1];
    const float* d_left  = (const float*)d_in[2];
    const float* d_right = (const float*)d_in[3];
    const float* nonocc  = (const float*)d_in[4];
    float* out = (float*)d_out;

    int B = in_sizes[2] / (IMG_H * IMG_W);   // d_left is [B,1,H,W]

    dim3 grid(IMG_W / TW, IMG_H / TH, B);
    int nblocks = grid.x * grid.y * grid.z;

    stereo_loss_kernel<<<grid, 256>>>(left, right, d_left, d_right, nonocc,
                                      out, nblocks, B * IMG_H * IMG_W);
}